// round 2
// baseline (speedup 1.0000x reference)
#include <cuda_runtime.h>
#include <float.h>
#include <math.h>

// Problem constants
constexpr int B  = 4;
constexpr int C  = 64;
constexpr int F  = 128;
constexpr int T  = 512;
constexpr int DC = 32;           // d_c
constexpr int NW = T / 32;       // 16 warps per CTA
constexpr int QSTRIDE = DC + 2;  // 34 floats: keeps 8B alignment, 2-way-max STS conflicts

// Dynamic smem layout (floats)
constexpr int OFF_QS   = 0;                         // [T][QSTRIDE]
constexpr int OFF_W1   = OFF_QS + T * QSTRIDE;      // [DC][C]
constexpr int OFF_WP   = OFF_W1 + DC * C;           // [C][DC]
constexpr int OFF_AL1  = OFF_WP + C * DC;           // [DC]
constexpr int OFF_BI1  = OFF_AL1 + DC;              // [DC]
constexpr int OFF_AL2  = OFF_BI1 + DC;              // [C]
constexpr int OFF_BI2  = OFF_AL2 + C;               // [C]
constexpr int OFF_REDM = OFF_BI2 + C;               // [DC][NW]
constexpr int OFF_REDS = OFF_REDM + DC * NW;        // [DC][NW]
constexpr int OFF_FINM = OFF_REDS + DC * NW;        // [DC]
constexpr int OFF_FINI = OFF_FINM + DC;             // [DC]
constexpr int SMEM_FLOATS = OFF_FINI + DC;
constexpr int SMEM_BYTES  = SMEM_FLOATS * 4;

#define DEVI __device__ __forceinline__

// Packed fp32x2 helpers (Blackwell FFMA2 — only reachable via PTX)
DEVI unsigned long long ffma2(unsigned long long a, unsigned long long b, unsigned long long c) {
    unsigned long long d;
    asm("fma.rn.f32x2 %0, %1, %2, %3;" : "=l"(d) : "l"(a), "l"(b), "l"(c));
    return d;
}
DEVI unsigned long long fadd2(unsigned long long a, unsigned long long b) {
    unsigned long long d;
    asm("add.rn.f32x2 %0, %1, %2;" : "=l"(d) : "l"(a), "l"(b));
    return d;
}
DEVI unsigned long long pack2(float lo, float hi) {
    unsigned long long d;
    asm("mov.b64 %0, {%1, %2};" : "=l"(d) : "f"(lo), "f"(hi));
    return d;
}
DEVI void unpack2(unsigned long long v, float& lo, float& hi) {
    asm("mov.b64 {%0, %1}, %2;" : "=f"(lo), "=f"(hi) : "l"(v));
}

__global__ __launch_bounds__(T, 1) void attn_fused_kernel(
    const float* __restrict__ inp, const float* __restrict__ w1, const float* __restrict__ b1,
    const float* __restrict__ g1,  const float* __restrict__ be1, const float* __restrict__ m1,
    const float* __restrict__ v1,  const float* __restrict__ a1p,
    const float* __restrict__ wp,  const float* __restrict__ bp,
    const float* __restrict__ g2,  const float* __restrict__ be2, const float* __restrict__ m2,
    const float* __restrict__ v2,  const float* __restrict__ a2p,
    float* __restrict__ out)
{
    extern __shared__ float sm[];
    float* QS   = sm + OFF_QS;
    float* W1S  = sm + OFF_W1;
    float* WPS  = sm + OFF_WP;
    float* AL1  = sm + OFF_AL1;
    float* BI1  = sm + OFF_BI1;
    float* AL2  = sm + OFF_AL2;
    float* BI2  = sm + OFF_BI2;
    float* REDM = sm + OFF_REDM;
    float* REDS = sm + OFF_REDS;
    float* FINM = sm + OFF_FINM;
    float* FINI = sm + OFF_FINI;

    const int bf   = blockIdx.x;
    const int b    = bf >> 7;          // F = 128
    const int f    = bf & (F - 1);
    const int t    = threadIdx.x;
    const int lane = t & 31;
    const int wrp  = t >> 5;

    // ---- weights / fused BN params into smem ----
    for (int i = t; i < DC * C; i += T) W1S[i] = w1[i];
    for (int i = t; i < C * DC; i += T) WPS[i] = wp[i];
    if (t < DC) {
        float sc = g1[t] / sqrtf(v1[t] + 1e-5f);
        AL1[t] = sc;
        BI1[t] = (b1[t] - m1[t]) * sc + be1[t];
    }
    if (t < C) {
        float sc = g2[t] / sqrtf(v2[t] + 1e-5f);
        AL2[t] = sc;
        BI2[t] = (bp[t] - m2[t]) * sc + be2[t];
    }
    __syncthreads();

    const float pr1 = a1p[0];
    const float pr2 = a2p[0];

    // ---- phase 0: conv1 (Cx1x1 -> DC) + BN + PReLU, one t-column per thread ----
    {
        float x[C];
        const float* xin = inp + ((size_t)b * C * F + f) * T + t;
        #pragma unroll
        for (int ci = 0; ci < C; ci++) x[ci] = xin[(size_t)ci * F * T];
        #pragma unroll
        for (int c = 0; c < DC; c++) {
            float s = 0.f;
            #pragma unroll
            for (int ci = 0; ci < C; ci++) s += W1S[c * C + ci] * x[ci];
            float z = s * AL1[c] + BI1[c];
            QS[t * QSTRIDE + c] = (z >= 0.f) ? z : pr1 * z;
        }
    }
    __syncthreads();

    // ---- phase 1: A[c,t] = sum_y (q_t . q_y / sqrt(dc)) * q_y[c], packed f32x2 over c ----
    const bool masked = (t - f) >= (T - F + 1);
    unsigned long long q2[DC / 2], acc2[DC / 2];
    {
        const float invs = 0.17677669529663687f;  // 1/sqrt(32)
        #pragma unroll
        for (int i = 0; i < DC / 2; i++) {
            float lo = QS[t * QSTRIDE + 2 * i]     * invs;
            float hi = QS[t * QSTRIDE + 2 * i + 1] * invs;
            q2[i]  = pack2(lo, hi);
            acc2[i] = 0ULL;
        }
    }
    if (!masked) {
        #pragma unroll 1
        for (int y = 0; y < T; y++) {
            const unsigned long long* qy =
                (const unsigned long long*)(QS + y * QSTRIDE);
            unsigned long long v[DC / 2];
            #pragma unroll
            for (int i = 0; i < DC / 2; i++) v[i] = qy[i];
            unsigned long long s0 = 0ULL, s1 = 0ULL;
            #pragma unroll
            for (int i = 0; i < DC / 2; i += 2) {
                s0 = ffma2(q2[i],     v[i],     s0);
                s1 = ffma2(q2[i + 1], v[i + 1], s1);
            }
            float d0, d1;
            unpack2(fadd2(s0, s1), d0, d1);
            float s = d0 + d1;                     // S[t,y] (already /sqrt(dc))
            unsigned long long s2 = pack2(s, s);
            #pragma unroll
            for (int i = 0; i < DC / 2; i++) acc2[i] = ffma2(s2, v[i], acc2[i]);
        }
    }
    float a[DC];
    #pragma unroll
    for (int i = 0; i < DC / 2; i++) unpack2(acc2[i], a[2 * i], a[2 * i + 1]);
    if (masked) {
        #pragma unroll
        for (int c = 0; c < DC; c++) a[c] = -FLT_MAX;
    }

    // ---- phase 2: softmax over t (cross-thread), per channel c ----
    // Stage A: warp-level max + expsum per c
    #pragma unroll
    for (int c = 0; c < DC; c++) {
        float wm = a[c];
        #pragma unroll
        for (int o = 16; o > 0; o >>= 1)
            wm = fmaxf(wm, __shfl_xor_sync(0xffffffffu, wm, o));
        float e = expf(a[c] - wm);
        a[c] = e;                                  // keep exp(a - warp_max)
        float ws = e;
        #pragma unroll
        for (int o = 16; o > 0; o >>= 1)
            ws += __shfl_xor_sync(0xffffffffu, ws, o);
        if (lane == 0) { REDM[c * NW + wrp] = wm; REDS[c * NW + wrp] = ws; }
    }
    __syncthreads();
    // Stage B: combine 16 warp partials per c
    if (t < DC) {
        float M = -FLT_MAX;
        #pragma unroll
        for (int w = 0; w < NW; w++) M = fmaxf(M, REDM[t * NW + w]);
        float S = 0.f;
        #pragma unroll
        for (int w = 0; w < NW; w++) S += REDS[t * NW + w] * expf(REDM[t * NW + w] - M);
        FINM[t] = M;
        FINI[t] = 1.f / S;
    }
    __syncthreads();
    // Stage C: finalize probabilities in registers
    float P[DC];
    #pragma unroll
    for (int c = 0; c < DC; c++) {
        float fac = expf(REDM[c * NW + wrp] - FINM[c]) * FINI[c];
        P[c] = a[c] * fac;
    }

    // ---- phase 3: conv2 (DC -> C) + BN + PReLU + residual, packed f32x2 ----
    unsigned long long P2[DC / 2];
    #pragma unroll
    for (int i = 0; i < DC / 2; i++) P2[i] = pack2(P[2 * i], P[2 * i + 1]);

    const size_t obase = ((size_t)b * C * F + f) * T + t;
    #pragma unroll
    for (int co = 0; co < C; co++) {
        const unsigned long long* wr = (const unsigned long long*)(WPS + co * DC);
        unsigned long long sd = 0ULL;
        #pragma unroll
        for (int i = 0; i < DC / 2; i++) sd = ffma2(P2[i], wr[i], sd);
        float lo, hi;
        unpack2(sd, lo, hi);
        float z = (lo + hi) * AL2[co] + BI2[co];
        z = (z >= 0.f) ? z : pr2 * z;
        size_t idx = obase + (size_t)co * F * T;
        out[idx] = z + inp[idx];
    }
}

extern "C" void kernel_launch(void* const* d_in, const int* in_sizes, int n_in,
                              void* d_out, int out_size) {
    const float* inp = (const float*)d_in[0];
    const float* w1  = (const float*)d_in[1];
    const float* b1  = (const float*)d_in[2];
    const float* g1  = (const float*)d_in[3];
    const float* be1 = (const float*)d_in[4];
    const float* m1  = (const float*)d_in[5];
    const float* v1  = (const float*)d_in[6];
    const float* a1  = (const float*)d_in[7];
    const float* wp  = (const float*)d_in[8];
    const float* bp  = (const float*)d_in[9];
    const float* g2  = (const float*)d_in[10];
    const float* be2 = (const float*)d_in[11];
    const float* m2  = (const float*)d_in[12];
    const float* v2  = (const float*)d_in[13];
    const float* a2  = (const float*)d_in[14];
    float* out = (float*)d_out;

    cudaFuncSetAttribute(attn_fused_kernel,
                         cudaFuncAttributeMaxDynamicSharedMemorySize, SMEM_BYTES);
    attn_fused_kernel<<<B * F, T, SMEM_BYTES>>>(
        inp, w1, b1, g1, be1, m1, v1, a1, wp, bp, g2, be2, m2, v2, a2, out);
}

// round 3
// speedup vs baseline: 3.0977x; 3.0977x over previous
#include <cuda_runtime.h>
#include <float.h>
#include <math.h>

// Problem constants
constexpr int B  = 4;
constexpr int C  = 64;
constexpr int F  = 128;
constexpr int T  = 512;
constexpr int DC = 32;           // d_c
constexpr int NW = T / 32;       // 16 warps per CTA

// Dynamic smem layout (floats)
constexpr int OFF_QT   = 0;                          // [DC][T]  (channel-major)
constexpr int OFF_W1T  = OFF_QT + DC * T;            // [C][DC]  (transposed conv1 weights)
constexpr int OFF_WPS  = OFF_W1T + C * DC;           // [C][DC]
constexpr int OFF_G    = OFF_WPS + C * DC;           // [DC][DC]
constexpr int OFF_AL1  = OFF_G + DC * DC;            // [DC]
constexpr int OFF_BI1  = OFF_AL1 + DC;               // [DC]
constexpr int OFF_AL2  = OFF_BI1 + DC;               // [C]
constexpr int OFF_BI2  = OFF_AL2 + C;                // [C]
constexpr int OFF_REDM = OFF_BI2 + C;                // [DC][NW]
constexpr int OFF_REDS = OFF_REDM + DC * NW;         // [DC][NW]
constexpr int OFF_FINM = OFF_REDS + DC * NW;         // [DC]
constexpr int OFF_FINI = OFF_FINM + DC;              // [DC]
constexpr int SMEM_FLOATS = OFF_FINI + DC;
constexpr int SMEM_BYTES  = SMEM_FLOATS * 4;

#define DEVI __device__ __forceinline__

// Packed fp32x2 helpers (Blackwell FFMA2 — only reachable via PTX)
DEVI unsigned long long ffma2(unsigned long long a, unsigned long long b, unsigned long long c) {
    unsigned long long d;
    asm("fma.rn.f32x2 %0, %1, %2, %3;" : "=l"(d) : "l"(a), "l"(b), "l"(c));
    return d;
}
DEVI unsigned long long pack2(float lo, float hi) {
    unsigned long long d;
    asm("mov.b64 %0, {%1, %2};" : "=l"(d) : "f"(lo), "f"(hi));
    return d;
}
DEVI void unpack2(unsigned long long v, float& lo, float& hi) {
    asm("mov.b64 {%0, %1}, %2;" : "=f"(lo), "=f"(hi) : "l"(v));
}

__global__ __launch_bounds__(T, 1) void attn_fused_kernel(
    const float* __restrict__ inp, const float* __restrict__ w1, const float* __restrict__ b1,
    const float* __restrict__ g1,  const float* __restrict__ be1, const float* __restrict__ m1,
    const float* __restrict__ v1,  const float* __restrict__ a1p,
    const float* __restrict__ wp,  const float* __restrict__ bp,
    const float* __restrict__ g2,  const float* __restrict__ be2, const float* __restrict__ m2,
    const float* __restrict__ v2,  const float* __restrict__ a2p,
    float* __restrict__ out)
{
    extern __shared__ float sm[];
    float* QT   = sm + OFF_QT;
    float* W1T  = sm + OFF_W1T;
    float* WPS  = sm + OFF_WPS;
    float* G    = sm + OFF_G;
    float* AL1  = sm + OFF_AL1;
    float* BI1  = sm + OFF_BI1;
    float* AL2  = sm + OFF_AL2;
    float* BI2  = sm + OFF_BI2;
    float* REDM = sm + OFF_REDM;
    float* REDS = sm + OFF_REDS;
    float* FINM = sm + OFF_FINM;
    float* FINI = sm + OFF_FINI;

    const int bf   = blockIdx.x;
    const int b    = bf >> 7;          // F = 128
    const int f    = bf & (F - 1);
    const int t    = threadIdx.x;
    const int lane = t & 31;
    const int wrp  = t >> 5;

    // ---- weights (conv1 transposed for f32x2 pairing) / fused BN params ----
    for (int i = t; i < C * DC; i += T) {
        int ci = i >> 5, c = i & (DC - 1);         // W1T[ci][c] = w1[c][ci]
        W1T[i] = w1[c * C + ci];
        WPS[i] = wp[i];
    }
    if (t < DC) {
        float sc = g1[t] * rsqrtf(v1[t] + 1e-5f);
        AL1[t] = sc;
        BI1[t] = (b1[t] - m1[t]) * sc + be1[t];
    }
    if (t < C) {
        float sc = g2[t] * rsqrtf(v2[t] + 1e-5f);
        AL2[t] = sc;
        BI2[t] = (bp[t] - m2[t]) * sc + be2[t];
    }
    __syncthreads();

    const float pr1 = a1p[0];
    const float pr2 = a2p[0];

    // ---- phase 0: conv1 (C -> DC) + BN + PReLU, one t-column per thread ----
    float q[DC];
    {
        unsigned long long s2[DC / 2];
        #pragma unroll
        for (int i = 0; i < DC / 2; i++) s2[i] = 0ULL;
        const float* xin = inp + ((size_t)b * C * F + f) * T + t;
        #pragma unroll 4
        for (int ci = 0; ci < C; ci++) {
            float xv = xin[(size_t)ci * F * T];
            unsigned long long x2 = pack2(xv, xv);
            const unsigned long long* wr = (const unsigned long long*)(W1T + ci * DC);
            #pragma unroll
            for (int i = 0; i < DC / 2; i++) s2[i] = ffma2(x2, wr[i], s2[i]);
        }
        #pragma unroll
        for (int i = 0; i < DC / 2; i++) unpack2(s2[i], q[2 * i], q[2 * i + 1]);
        #pragma unroll
        for (int c = 0; c < DC; c++) {
            float z = q[c] * AL1[c] + BI1[c];
            z = (z >= 0.f) ? z : pr1 * z;
            q[c] = z;
            QT[c * T + t] = z;
        }
    }
    __syncthreads();

    // ---- phase 1: Gram matrix G = (Q Q^T) / sqrt(dc), 32x32 ----
    // Warp w computes rows {2w, 2w+1}; lanes partition t in float4 chunks.
    {
        const int c0 = wrp * 2;
        float4 r0[4], r1[4];
        #pragma unroll
        for (int j = 0; j < 4; j++) {
            r0[j] = *(const float4*)(QT + c0 * T + j * 128 + lane * 4);
            r1[j] = *(const float4*)(QT + (c0 + 1) * T + j * 128 + lane * 4);
        }
        const float invs = 0.17677669529663687f;   // 1/sqrt(32)
        #pragma unroll 4
        for (int cp = 0; cp < DC; cp++) {
            float a0 = 0.f, a1 = 0.f;
            #pragma unroll
            for (int j = 0; j < 4; j++) {
                float4 v = *(const float4*)(QT + cp * T + j * 128 + lane * 4);
                a0 += r0[j].x * v.x + r0[j].y * v.y + r0[j].z * v.z + r0[j].w * v.w;
                a1 += r1[j].x * v.x + r1[j].y * v.y + r1[j].z * v.z + r1[j].w * v.w;
            }
            #pragma unroll
            for (int o = 16; o > 0; o >>= 1) {
                a0 += __shfl_xor_sync(0xffffffffu, a0, o);
                a1 += __shfl_xor_sync(0xffffffffu, a1, o);
            }
            if (lane == 0) {
                G[c0 * DC + cp]       = a0 * invs;
                G[(c0 + 1) * DC + cp] = a1 * invs;
            }
        }
    }
    __syncthreads();

    // ---- phase 2: A[c,t] = sum_c' G[c,c'] q[c'], then mask ----
    const bool masked = (t - f) >= (T - F + 1);
    float aa[DC];
    {
        unsigned long long q2[DC / 2];
        #pragma unroll
        for (int i = 0; i < DC / 2; i++) q2[i] = pack2(q[2 * i], q[2 * i + 1]);
        #pragma unroll
        for (int c = 0; c < DC; c++) {
            const unsigned long long* gr = (const unsigned long long*)(G + c * DC);
            unsigned long long s0 = 0ULL, s1 = 0ULL;
            #pragma unroll
            for (int i = 0; i < DC / 2; i += 2) {
                s0 = ffma2(q2[i],     gr[i],     s0);
                s1 = ffma2(q2[i + 1], gr[i + 1], s1);
            }
            float d0, d1, d2, d3;
            unpack2(s0, d0, d1);
            unpack2(s1, d2, d3);
            aa[c] = (d0 + d1) + (d2 + d3);
        }
    }
    if (masked) {
        #pragma unroll
        for (int c = 0; c < DC; c++) aa[c] = -FLT_MAX;
    }

    // ---- phase 3: softmax over t (cross-thread), per channel c ----
    #pragma unroll
    for (int c = 0; c < DC; c++) {
        float wm = aa[c];
        #pragma unroll
        for (int o = 16; o > 0; o >>= 1)
            wm = fmaxf(wm, __shfl_xor_sync(0xffffffffu, wm, o));
        float e = expf(aa[c] - wm);
        aa[c] = e;                                 // keep exp(a - warp_max)
        float ws = e;
        #pragma unroll
        for (int o = 16; o > 0; o >>= 1)
            ws += __shfl_xor_sync(0xffffffffu, ws, o);
        if (lane == 0) { REDM[c * NW + wrp] = wm; REDS[c * NW + wrp] = ws; }
    }
    __syncthreads();
    if (t < DC) {
        float M = -FLT_MAX;
        #pragma unroll
        for (int w = 0; w < NW; w++) M = fmaxf(M, REDM[t * NW + w]);
        float S = 0.f;
        #pragma unroll
        for (int w = 0; w < NW; w++) S += REDS[t * NW + w] * expf(REDM[t * NW + w] - M);
        FINM[t] = M;
        FINI[t] = 1.f / S;
    }
    __syncthreads();
    float P[DC];
    #pragma unroll
    for (int c = 0; c < DC; c++) {
        float fac = expf(REDM[c * NW + wrp] - FINM[c]) * FINI[c];
        P[c] = aa[c] * fac;
    }

    // ---- phase 4: conv2 (DC -> C) + BN + PReLU + residual ----
    unsigned long long P2[DC / 2];
    #pragma unroll
    for (int i = 0; i < DC / 2; i++) P2[i] = pack2(P[2 * i], P[2 * i + 1]);

    const size_t obase = ((size_t)b * C * F + f) * T + t;
    #pragma unroll 4
    for (int co = 0; co < C; co++) {
        const unsigned long long* wr = (const unsigned long long*)(WPS + co * DC);
        unsigned long long s0 = 0ULL, s1 = 0ULL;
        #pragma unroll
        for (int i = 0; i < DC / 2; i += 2) {
            s0 = ffma2(P2[i],     wr[i],     s0);
            s1 = ffma2(P2[i + 1], wr[i + 1], s1);
        }
        float d0, d1, d2, d3;
        unpack2(s0, d0, d1);
        unpack2(s1, d2, d3);
        float z = ((d0 + d1) + (d2 + d3)) * AL2[co] + BI2[co];
        z = (z >= 0.f) ? z : pr2 * z;
        size_t idx = obase + (size_t)co * F * T;
        out[idx] = z + inp[idx];
    }
}

extern "C" void kernel_launch(void* const* d_in, const int* in_sizes, int n_in,
                              void* d_out, int out_size) {
    const float* inp = (const float*)d_in[0];
    const float* w1  = (const float*)d_in[1];
    const float* b1  = (const float*)d_in[2];
    const float* g1  = (const float*)d_in[3];
    const float* be1 = (const float*)d_in[4];
    const float* m1  = (const float*)d_in[5];
    const float* v1  = (const float*)d_in[6];
    const float* a1  = (const float*)d_in[7];
    const float* wp  = (const float*)d_in[8];
    const float* bp  = (const float*)d_in[9];
    const float* g2  = (const float*)d_in[10];
    const float* be2 = (const float*)d_in[11];
    const float* m2  = (const float*)d_in[12];
    const float* v2  = (const float*)d_in[13];
    const float* a2  = (const float*)d_in[14];
    float* out = (float*)d_out;

    cudaFuncSetAttribute(attn_fused_kernel,
                         cudaFuncAttributeMaxDynamicSharedMemorySize, SMEM_BYTES);
    attn_fused_kernel<<<B * F, T, SMEM_BYTES>>>(
        inp, w1, b1, g1, be1, m1, v1, a1, wp, bp, g2, be2, m2, v2, a2, out);
}

// round 7
// speedup vs baseline: 3.2519x; 1.0498x over previous
#include <cuda_runtime.h>
#include <float.h>
#include <math.h>

// Problem constants
constexpr int B  = 4;
constexpr int C  = 64;
constexpr int F  = 128;
constexpr int T  = 512;
constexpr int DC = 32;           // d_c
constexpr int NW = T / 32;       // 16 warps per CTA
constexpr int QSTR = 36;         // [t][c] row stride: 144B -> every row 16B aligned
constexpr int GPSTR = 34;        // partial-G row stride (words), 8B-aligned rows

// Dynamic smem layout (floats)
constexpr int OFF_QS   = 0;                          // [T][QSTR]   (t-major Q)
constexpr int OFF_W1T  = OFF_QS + T * QSTR;          // [C][DC]     (transposed conv1 weights)
constexpr int OFF_WPS  = OFF_W1T + C * DC;           // [C][DC]
constexpr int OFF_G    = OFF_WPS + C * DC;           // [DC][DC]
constexpr int OFF_GP   = OFF_G + DC * DC;            // [NW*32][GPSTR] partials
constexpr int OFF_AL1  = OFF_GP + NW * 32 * GPSTR;   // [DC]
constexpr int OFF_BI1  = OFF_AL1 + DC;               // [DC]
constexpr int OFF_AL2  = OFF_BI1 + DC;               // [C]
constexpr int OFF_BI2  = OFF_AL2 + C;                // [C]
constexpr int OFF_REDM = OFF_BI2 + C;                // [DC][NW]
constexpr int OFF_REDS = OFF_REDM + DC * NW;         // [DC][NW]
constexpr int OFF_FINM = OFF_REDS + DC * NW;         // [DC]
constexpr int OFF_FINI = OFF_FINM + DC;              // [DC]
constexpr int SMEM_FLOATS = OFF_FINI + DC;
constexpr int SMEM_BYTES  = SMEM_FLOATS * 4;

#define DEVI __device__ __forceinline__

// Packed fp32x2 helpers (Blackwell FFMA2 — only reachable via PTX)
DEVI unsigned long long ffma2(unsigned long long a, unsigned long long b, unsigned long long c) {
    unsigned long long d;
    asm("fma.rn.f32x2 %0, %1, %2, %3;" : "=l"(d) : "l"(a), "l"(b), "l"(c));
    return d;
}
DEVI unsigned long long fadd2(unsigned long long a, unsigned long long b) {
    unsigned long long d;
    asm("add.rn.f32x2 %0, %1, %2;" : "=l"(d) : "l"(a), "l"(b));
    return d;
}
DEVI unsigned long long pack2(float lo, float hi) {
    unsigned long long d;
    asm("mov.b64 %0, {%1, %2};" : "=l"(d) : "f"(lo), "f"(hi));
    return d;
}
DEVI void unpack2(unsigned long long v, float& lo, float& hi) {
    asm("mov.b64 {%0, %1}, %2;" : "=f"(lo), "=f"(hi) : "l"(v));
}

__global__ __launch_bounds__(T, 1) void attn_fused_kernel(
    const float* __restrict__ inp, const float* __restrict__ w1, const float* __restrict__ b1,
    const float* __restrict__ g1,  const float* __restrict__ be1, const float* __restrict__ m1,
    const float* __restrict__ v1,  const float* __restrict__ a1p,
    const float* __restrict__ wp,  const float* __restrict__ bp,
    const float* __restrict__ g2,  const float* __restrict__ be2, const float* __restrict__ m2,
    const float* __restrict__ v2,  const float* __restrict__ a2p,
    float* __restrict__ out)
{
    extern __shared__ float sm[];
    float* QS   = sm + OFF_QS;
    float* W1T  = sm + OFF_W1T;
    float* WPS  = sm + OFF_WPS;
    float* G    = sm + OFF_G;
    float* GP   = sm + OFF_GP;
    float* AL1  = sm + OFF_AL1;
    float* BI1  = sm + OFF_BI1;
    float* AL2  = sm + OFF_AL2;
    float* BI2  = sm + OFF_BI2;
    float* REDM = sm + OFF_REDM;
    float* REDS = sm + OFF_REDS;
    float* FINM = sm + OFF_FINM;
    float* FINI = sm + OFF_FINI;

    const int bf   = blockIdx.x;
    const int b    = bf >> 7;          // F = 128
    const int f    = bf & (F - 1);
    const int t    = threadIdx.x;
    const int lane = t & 31;
    const int wrp  = t >> 5;

    // ---- weights (conv1 transposed for f32x2 pairing) / fused BN params ----
    for (int i = t; i < C * DC; i += T) {
        int ci = i >> 5, c = i & (DC - 1);         // W1T[ci][c] = w1[c][ci]
        W1T[i] = w1[c * C + ci];
        WPS[i] = wp[i];
    }
    if (t < DC) {
        float sc = g1[t] * rsqrtf(v1[t] + 1e-5f);
        AL1[t] = sc;
        BI1[t] = (b1[t] - m1[t]) * sc + be1[t];
    }
    if (t < C) {
        float sc = g2[t] * rsqrtf(v2[t] + 1e-5f);
        AL2[t] = sc;
        BI2[t] = (bp[t] - m2[t]) * sc + be2[t];
    }
    __syncthreads();

    const float pr1 = a1p[0];
    const float pr2 = a2p[0];

    // ---- phase 0: conv1 (C -> DC) + BN + PReLU, one t-column per thread ----
    float q[DC];
    {
        unsigned long long s2[DC / 2];
        #pragma unroll
        for (int i = 0; i < DC / 2; i++) s2[i] = 0ULL;
        const float* xin = inp + ((size_t)b * C * F + f) * T + t;
        #pragma unroll 4
        for (int ci = 0; ci < C; ci++) {
            float xv = xin[(size_t)ci * F * T];
            unsigned long long x2 = pack2(xv, xv);
            const ulonglong2* wr = (const ulonglong2*)(W1T + ci * DC);
            #pragma unroll
            for (int k = 0; k < DC / 4; k++) {          // 8 LDS.128
                ulonglong2 wv = wr[k];
                s2[2 * k]     = ffma2(x2, wv.x, s2[2 * k]);
                s2[2 * k + 1] = ffma2(x2, wv.y, s2[2 * k + 1]);
            }
        }
        #pragma unroll
        for (int i = 0; i < DC / 2; i++) unpack2(s2[i], q[2 * i], q[2 * i + 1]);
        #pragma unroll
        for (int c = 0; c < DC; c++) {
            float z = q[c] * AL1[c] + BI1[c];
            q[c] = (z >= 0.f) ? z : pr1 * z;
        }
        float* row = QS + t * QSTR;
        #pragma unroll
        for (int i = 0; i < DC / 4; i++)               // 8 STS.128
            *(float4*)(row + 4 * i) = make_float4(q[4 * i], q[4 * i + 1], q[4 * i + 2], q[4 * i + 3]);
    }
    __syncthreads();

    // ---- phase 1: Gram via per-warp rank-1 updates over its 32-t slice ----
    {
        unsigned long long acc2[DC / 2];
        #pragma unroll
        for (int i = 0; i < DC / 2; i++) acc2[i] = 0ULL;
        const float* base = QS + (wrp * 32) * QSTR;
        #pragma unroll 8
        for (int s = 0; s < 32; s++) {
            const float* row = base + s * QSTR;
            float ql = row[lane];                      // conflict-free LDS.32
            unsigned long long sp = pack2(ql, ql);
            const ulonglong2* rp = (const ulonglong2*)row;
            #pragma unroll
            for (int k = 0; k < DC / 4; k++) {         // 8 broadcast LDS.128
                ulonglong2 v = rp[k];
                acc2[2 * k]     = ffma2(sp, v.x, acc2[2 * k]);
                acc2[2 * k + 1] = ffma2(sp, v.y, acc2[2 * k + 1]);
            }
        }
        // store partials: GP[(wrp*32+lane)][GPSTR]
        float* prow = GP + (wrp * 32 + lane) * GPSTR;
        #pragma unroll
        for (int i = 0; i < DC / 2; i++)
            *(unsigned long long*)(prow + 2 * i) = acc2[i];
    }
    __syncthreads();
    // reduce 16 warp partials: thread owns entry pair (c, 2j..2j+1)
    {
        const int c = t >> 4, j = t & 15;
        unsigned long long acc = 0ULL;
        #pragma unroll
        for (int w = 0; w < NW; w++)
            acc = fadd2(acc, *(const unsigned long long*)(GP + (w * 32 + c) * GPSTR + 2 * j));
        const float invs = 0.17677669529663687f;       // 1/sqrt(32)
        float lo, hi;
        unpack2(acc, lo, hi);
        *(unsigned long long*)(G + c * DC + 2 * j) = pack2(lo * invs, hi * invs);
    }
    __syncthreads();

    // ---- phase 2: A[c,t] = sum_c' G[c,c'] q[c'], then mask ----
    const bool masked = (t - f) >= (T - F + 1);
    float aa[DC];
    {
        unsigned long long q2[DC / 2];
        #pragma unroll
        for (int i = 0; i < DC / 2; i++) q2[i] = pack2(q[2 * i], q[2 * i + 1]);
        #pragma unroll
        for (int c = 0; c < DC; c++) {
            const ulonglong2* gr = (const ulonglong2*)(G + c * DC);
            unsigned long long s0 = 0ULL, s1 = 0ULL;
            #pragma unroll
            for (int k = 0; k < DC / 4; k++) {         // 8 broadcast LDS.128
                ulonglong2 gv = gr[k];
                s0 = ffma2(q2[2 * k],     gv.x, s0);
                s1 = ffma2(q2[2 * k + 1], gv.y, s1);
            }
            float d0, d1, d2, d3;
            unpack2(s0, d0, d1);
            unpack2(s1, d2, d3);
            aa[c] = (d0 + d1) + (d2 + d3);
        }
    }
    if (masked) {
        #pragma unroll
        for (int c = 0; c < DC; c++) aa[c] = -FLT_MAX;
    }

    // ---- phase 3: softmax over t (cross-thread), per channel c ----
    #pragma unroll
    for (int c = 0; c < DC; c++) {
        float wm = aa[c];
        #pragma unroll
        for (int o = 16; o > 0; o >>= 1)
            wm = fmaxf(wm, __shfl_xor_sync(0xffffffffu, wm, o));
        float e = __expf(aa[c] - wm);
        aa[c] = e;                                     // keep exp(a - warp_max)
        float ws = e;
        #pragma unroll
        for (int o = 16; o > 0; o >>= 1)
            ws += __shfl_xor_sync(0xffffffffu, ws, o);
        if (lane == 0) { REDM[c * NW + wrp] = wm; REDS[c * NW + wrp] = ws; }
    }
    __syncthreads();
    if (t < DC) {
        float M = -FLT_MAX;
        #pragma unroll
        for (int w = 0; w < NW; w++) M = fmaxf(M, REDM[t * NW + w]);
        float S = 0.f;
        #pragma unroll
        for (int w = 0; w < NW; w++) S += REDS[t * NW + w] * __expf(REDM[t * NW + w] - M);
        FINM[t] = M;
        FINI[t] = 1.f / S;
    }
    __syncthreads();
    float P[DC];
    #pragma unroll
    for (int c = 0; c < DC; c++) {
        float fac = __expf(REDM[c * NW + wrp] - FINM[c]) * FINI[c];
        P[c] = aa[c] * fac;
    }

    // ---- phase 4: conv2 (DC -> C) + BN + PReLU + residual ----
    unsigned long long P2[DC / 2];
    #pragma unroll
    for (int i = 0; i < DC / 2; i++) P2[i] = pack2(P[2 * i], P[2 * i + 1]);

    const size_t obase = ((size_t)b * C * F + f) * T + t;
    #pragma unroll 4
    for (int co = 0; co < C; co++) {
        const ulonglong2* wr = (const ulonglong2*)(WPS + co * DC);
        unsigned long long s0 = 0ULL, s1 = 0ULL;
        #pragma unroll
        for (int k = 0; k < DC / 4; k++) {             // 8 broadcast LDS.128
            ulonglong2 wv = wr[k];
            s0 = ffma2(P2[2 * k],     wv.x, s0);
            s1 = ffma2(P2[2 * k + 1], wv.y, s1);
        }
        float d0, d1, d2, d3;
        unpack2(s0, d0, d1);
        unpack2(s1, d2, d3);
        float z = ((d0 + d1) + (d2 + d3)) * AL2[co] + BI2[co];
        z = (z >= 0.f) ? z : pr2 * z;
        size_t idx = obase + (size_t)co * F * T;
        out[idx] = z + inp[idx];
    }
}

extern "C" void kernel_launch(void* const* d_in, const int* in_sizes, int n_in,
                              void* d_out, int out_size) {
    const float* inp = (const float*)d_in[0];
    const float* w1  = (const float*)d_in[1];
    const float* b1  = (const float*)d_in[2];
    const float* g1  = (const float*)d_in[3];
    const float* be1 = (const float*)d_in[4];
    const float* m1  = (const float*)d_in[5];
    const float* v1  = (const float*)d_in[6];
    const float* a1  = (const float*)d_in[7];
    const float* wp  = (const float*)d_in[8];
    const float* bp  = (const float*)d_in[9];
    const float* g2  = (const float*)d_in[10];
    const float* be2 = (const float*)d_in[11];
    const float* m2  = (const float*)d_in[12];
    const float* v2  = (const float*)d_in[13];
    const float* a2  = (const float*)d_in[14];
    float* out = (float*)d_out;

    cudaFuncSetAttribute(attn_fused_kernel,
                         cudaFuncAttributeMaxDynamicSharedMemorySize, SMEM_BYTES);
    attn_fused_kernel<<<B * F, T, SMEM_BYTES>>>(
        inp, w1, b1, g1, be1, m1, v1, a1, wp, bp, g2, be2, m2, v2, a2, out);
}